// round 14
// baseline (speedup 1.0000x reference)
#include <cuda_runtime.h>
#include <cuda_bf16.h>
#include <math.h>

// Problem constants
#define BB 8
#define CC 19
#define HH 512
#define WW 512
#define HW (HH*WW)          // 262144
#define NPLANE 16           // 8 pred-planes + 8 label-planes
#define NHC 64              // h-chunks in k_part (8 rows each)

// padded image: 2px clamp halo, pitch 528 (16B aligned), origin (2,4)
#define PPITCH 528
#define PROWS  516
#define PSIZE  (PROWS*PPITCH)

// ---------------- device scratch (static, no allocation) ----------------
__device__ unsigned char g_imgp[NPLANE*PSIZE];   // padded quantized images
__device__ unsigned char g_state[NPLANE*HW];     // 0/1/2 states, then edge bytes after k_edge
__device__ int           g_label[NPLANE*HW];     // union-find labels (valid where state>0)
__device__ unsigned char g_flag[NPLANE*HW];      // component-has-strong (by root)
__device__ int   g_pnp[NHC][BB*WW];
__device__ int   g_pnl[NHC][BB*WW];
__device__ int   g_pdt[NHC][BB*WW];

// write a quad + clamp-halo replicas into a padded plane
__device__ __forceinline__ void store_quad(unsigned char* plane, int y, int x, uchar4 q)
{
    int py = y + 2, px = x + 4;
    *reinterpret_cast<uchar4*>(plane + py*PPITCH + px) = q;
    bool top = (y == 0), bot = (y == HH-1);
    if (top) {
        *reinterpret_cast<uchar4*>(plane + 0*PPITCH + px) = q;
        *reinterpret_cast<uchar4*>(plane + 1*PPITCH + px) = q;
    }
    if (bot) {
        *reinterpret_cast<uchar4*>(plane + 514*PPITCH + px) = q;
        *reinterpret_cast<uchar4*>(plane + 515*PPITCH + px) = q;
    }
    if (x == 0) {
        uchar4 l = make_uchar4(q.x, q.x, q.x, q.x);
        *reinterpret_cast<uchar4*>(plane + py*PPITCH + 0) = l;
        if (top) { *reinterpret_cast<uchar4*>(plane + 0*PPITCH) = l;
                   *reinterpret_cast<uchar4*>(plane + 1*PPITCH) = l; }
        if (bot) { *reinterpret_cast<uchar4*>(plane + 514*PPITCH) = l;
                   *reinterpret_cast<uchar4*>(plane + 515*PPITCH) = l; }
    }
    if (x == WW-4) {
        uchar4 r = make_uchar4(q.w, q.w, q.w, q.w);
        *reinterpret_cast<uchar4*>(plane + py*PPITCH + 516) = r;
        if (top) { *reinterpret_cast<uchar4*>(plane + 0*PPITCH + 516) = r;
                   *reinterpret_cast<uchar4*>(plane + 1*PPITCH + 516) = r; }
        if (bot) { *reinterpret_cast<uchar4*>(plane + 514*PPITCH + 516) = r;
                   *reinterpret_cast<uchar4*>(plane + 515*PPITCH + 516) = r; }
    }
}

// ---------------- K1: argmax over C + quantize -> padded images (halo inline) ----------------
__global__ void k_prepare(const float* __restrict__ pred,
                          const float* __restrict__ labels)
{
    int b  = blockIdx.y;
    int i4 = blockIdx.x * blockDim.x + threadIdx.x;   // float4 index in HW/4
    if (i4 >= HW/4) return;

    const float4* base = reinterpret_cast<const float4*>(pred + (size_t)b*CC*HW) + i4;
    float4 best = base[0];
    int bx = 0, by = 0, bz = 0, bw = 0;
    #pragma unroll
    for (int c = 1; c < CC; c++) {
        float4 v = base[(size_t)c * (HW/4)];
        if (v.x > best.x) { best.x = v.x; bx = c; }
        if (v.y > best.y) { best.y = v.y; by = c; }
        if (v.z > best.z) { best.z = v.z; bz = c; }
        if (v.w > best.w) { best.w = v.w; bw = c; }
    }
    // (cls*255) % 256 == 0 if cls==0 else 256-cls  (cls in 0..18)
    uchar4 op;
    op.x = bx ? (unsigned char)(256 - bx) : 0;
    op.y = by ? (unsigned char)(256 - by) : 0;
    op.z = bz ? (unsigned char)(256 - bz) : 0;
    op.w = bw ? (unsigned char)(256 - bw) : 0;

    int pix = i4 * 4;
    int y = pix >> 9, x = pix & 511;
    store_quad(g_imgp + (size_t)b*PSIZE, y, x, op);

    float4 l = reinterpret_cast<const float4*>(labels + (size_t)b*HW)[i4];
    uchar4 ol;
    ol.x = (unsigned char)floorf(l.x * 255.0f);
    ol.y = (unsigned char)floorf(l.y * 255.0f);
    ol.z = (unsigned char)floorf(l.z * 255.0f);
    ol.w = (unsigned char)floorf(l.w * 255.0f);
    store_quad(g_imgp + (size_t)(8+b)*PSIZE, y, x, ol);
}

// ---------------- smem union-find (tile-local CCL) ----------------
__device__ __forceinline__ int findrootS(volatile int* L, int x)
{
    int p = L[x];
    while (p != x) { x = p; p = L[x]; }
    return p;
}

__device__ __forceinline__ void uniteS(volatile int* L, int a, int b)
{
    while (true) {
        a = findrootS(L, a);
        b = findrootS(L, b);
        if (a == b) return;
        if (a < b) { int t = a; a = b; b = t; }
        int old = atomicMin((int*)&L[a], b);
        if (old == a) return;
        a = old;
    }
}

// ---------------- K2: Sobel + NMS + tile-local union-find ----------------
__global__ void k_canny()
{
    __shared__ unsigned int simg_u[36*10];   // 36 rows x 40 bytes
    __shared__ int          smag[34][36];
    __shared__ unsigned char sst[32][32];
    __shared__ int          sl[1024];
    unsigned char* simg = (unsigned char*)simg_u;

    const int plane = blockIdx.z;
    const int oy = blockIdx.y * 32;
    const int ox = blockIdx.x * 32;
    const int tx = threadIdx.x, ty = threadIdx.y;
    const int tid = ty * 32 + tx;
    const unsigned char* img = g_imgp + (size_t)plane * PSIZE;

    for (int i = tid; i < 360; i += 1024) {
        int sy = i / 10, j = i % 10;
        simg_u[sy*10 + j] =
            *reinterpret_cast<const unsigned int*>(img + (oy + sy)*PPITCH + ox + 4*j);
    }
    __syncthreads();

    for (int i = tid; i < 34*34; i += 1024) {
        int sy = i / 34, sx = i % 34;
        int my = oy + sy - 1, mx = ox + sx - 1;
        int m = 0;
        if (my >= 0 && my < HH && mx >= 0 && mx < WW) {
            const unsigned char* r0p = simg + sy*40 + sx + 2;
            const unsigned char* r1p = r0p + 40;
            const unsigned char* r2p = r1p + 40;
            int a00 = r0p[0], a01 = r0p[1], a02 = r0p[2];
            int a10 = r1p[0],               a12 = r1p[2];
            int a20 = r2p[0], a21 = r2p[1], a22 = r2p[2];
            int gxv = (a02 + 2*a12 + a22) - (a00 + 2*a10 + a20);
            int gyv = (a20 + 2*a21 + a22) - (a00 + 2*a01 + a02);
            m = abs(gxv) + abs(gyv);
        }
        smag[sy][sx] = m;
    }
    __syncthreads();

    const int i1 = ty + 1, j1 = tx + 1;
    {
        const unsigned char* r0p = simg + (ty+1)*40 + tx + 3;
        const unsigned char* r1p = r0p + 40;
        const unsigned char* r2p = r1p + 40;
        int a00 = r0p[0], a01 = r0p[1], a02 = r0p[2];
        int a10 = r1p[0],               a12 = r1p[2];
        int a20 = r2p[0], a21 = r2p[1], a22 = r2p[2];
        int gxv = (a02 + 2*a12 + a22) - (a00 + 2*a10 + a20);
        int gyv = (a20 + 2*a21 + a22) - (a00 + 2*a01 + a02);
        int m = smag[i1][j1];

        int a = abs(gxv);
        int gyn = gyv, sgx = gxv;
        if (gyn < 0) { gyn = -gyn; sgx = -sgx; }
        int u = gyn + a;
        bool d0  = (u*u < 2*a*a);                 // |tan| < tan22.5
        int v = gyn - a;
        bool lt2 = (v < 0) || (v*v < 2*a*a);      // |tan| < tan67.5

        bool keep;
        if (d0)                   keep = (m >= smag[i1][j1+1]) && (m >= smag[i1][j1-1]);
        else if (sgx > 0 && lt2)  keep = (m >= smag[i1-1][j1+1]) && (m >= smag[i1+1][j1-1]);
        else if (!lt2)            keep = (m >= smag[i1+1][j1]) && (m >= smag[i1-1][j1]);
        else                      keep = (m >= smag[i1-1][j1-1]) && (m >= smag[i1+1][j1+1]);

        unsigned char st = 0;
        if (keep) { if (m > 200) st = 2; else if (m > 100) st = 1; }
        sst[ty][tx] = st;
    }
    sl[tid] = tid;
    __syncthreads();

    unsigned char st = sst[ty][tx];
    if (st) {
        if (tx > 0           && sst[ty][tx-1])   uniteS(sl, tid, tid-1);
        if (ty > 0) {
            if (tx > 0       && sst[ty-1][tx-1]) uniteS(sl, tid, tid-33);
            if (                sst[ty-1][tx])   uniteS(sl, tid, tid-32);
            if (tx < 31      && sst[ty-1][tx+1]) uniteS(sl, tid, tid-31);
        }
    }
    __syncthreads();

    int gidx = plane*HW + (oy+ty)*WW + (ox+tx);
    g_state[gidx] = st;
    if (st) {
        int root = findrootS(sl, tid);
        g_label[gidx] = plane*HW + (oy + (root >> 5))*WW + (ox + (root & 31));
        g_flag[gidx]  = 0;
    }
}

// ---------------- global union-find ----------------
__device__ __forceinline__ int findroot(int* L, int x)
{
    int p = __ldcg(&L[x]);
    while (p != x) { x = p; p = __ldcg(&L[x]); }
    return p;
}

__device__ __forceinline__ void unite(int* L, int a, int b)
{
    while (true) {
        a = findroot(L, a);
        b = findroot(L, b);
        if (a == b) return;
        if (a < b) { int t = a; a = b; b = t; }
        int old = atomicMin(&L[a], b);
        if (old == a) return;
        a = old;
    }
}

__device__ __forceinline__ int findhalve(int* L, int x)
{
    while (true) {
        int p = __ldcg(&L[x]);
        if (p == x) return x;
        int gp = __ldcg(&L[p]);
        if (gp == p) return p;
        L[x] = gp;
        x = gp;
    }
}

// ---------------- K3: cross-tile merges, compact boundary enumeration ----------------
#define TPP (8192 + 7680 + 7680)
__global__ void k_merge()
{
    int t = blockIdx.x * blockDim.x + threadIdx.x;
    if (t >= NPLANE*TPP) return;
    int plane = t / TPP;
    int i = t % TPP;

    int x, y;
    bool doW = false, doNW = false, doN = false, doNE = false;
    if (i < 8192) {
        y = (i >> 9) * 32; x = i & 511;
        doNW = doN = doNE = true; doW = ((x & 31) == 0);
    } else if (i < 8192 + 7680) {
        int j = i - 8192; y = j & 511; x = 32 * ((j >> 9) + 1);
        if ((y & 31) == 0) return;
        doW = doNW = true;
    } else {
        int j = i - 8192 - 7680; y = j & 511; x = 32 * (j >> 9) + 31;
        if ((y & 31) == 0) return;
        doNE = true;
    }

    int idx = plane*HW + y*WW + x;
    if (!g_state[idx]) return;
    if (doW && x > 0 && g_state[idx-1]) unite(g_label, idx, idx-1);
    if (y > 0) {
        if (doNW && x > 0    && g_state[idx-WW-1]) unite(g_label, idx, idx-WW-1);
        if (doN              && g_state[idx-WW])   unite(g_label, idx, idx-WW);
        if (doNE && x < WW-1 && g_state[idx-WW+1]) unite(g_label, idx, idx-WW+1);
    }
}

// ---------------- K4: mark strong components (4 px/thread — measured best) ----------------
__global__ void k_flag()
{
    int t = blockIdx.x * blockDim.x + threadIdx.x;
    if (t >= NPLANE*HW/4) return;
    unsigned int w = reinterpret_cast<const unsigned int*>(g_state)[t];
    if ((w & 0x02020202u) == 0) return;
    int base = t * 4;
    #pragma unroll
    for (int j = 0; j < 4; j++) {
        if ((w >> (8*j)) & 2u) {
            g_flag[findhalve(g_label, base + j)] = 1;
        }
    }
}

// ---------------- K4b: resolve pixels to edge bytes (1 px/thread — measured best) ----------------
__global__ void k_edge()
{
    int idx = blockIdx.x * blockDim.x + threadIdx.x;
    if (idx >= NPLANE*HW) return;
    unsigned char s = g_state[idx];
    unsigned char e = 0;
    if (s == 2) e = 1;
    else if (s == 1) e = g_flag[findhalve(g_label, idx)];
    g_state[idx] = e;      // in-place: g_state now holds edge map {0,1}
}

// ---------------- K5: per-column partial sums — pure streaming ----------------
__global__ void k_part()
{
    int b  = blockIdx.y;          // batch
    int hc = blockIdx.x;          // h-chunk of 8 rows
    int w  = threadIdx.x;         // 512 threads = one per column
    int np = 0, nl = 0, dt = 0;
    int base_p = b*HW       + hc*8*WW + w;
    int base_l = (8+b)*HW   + hc*8*WW + w;
    #pragma unroll
    for (int hh = 0; hh < 8; hh++) {
        int ep = g_state[base_p + hh*WW];
        int el = g_state[base_l + hh*WW];
        np += ep; nl += el; dt += (ep & el);
    }
    int col = b*WW + w;
    g_pnp[hc][col] = np;
    g_pnl[hc][col] = nl;
    g_pdt[hc][col] = dt;
}

// ---------------- K6: column losses + final scalar (single block) ----------------
__global__ void k_final(float* __restrict__ out)
{
    __shared__ float red[1024];
    float acc = 0.0f;
    #pragma unroll
    for (int k = 0; k < 4; k++) {
        int col = threadIdx.x + k*1024;
        int np = 0, nl = 0, dt = 0;
        #pragma unroll 8
        for (int hc = 0; hc < NHC; hc++) {
            np += g_pnp[hc][col];
            nl += g_pnl[hc][col];
            dt += g_pdt[hc][col];
        }
        float lse = logf(fmaf((float)np, 1.7182818284590452f, 512.0f));
        acc += (float)nl * lse - (float)dt;
    }
    red[threadIdx.x] = acc;
    __syncthreads();
    for (int s = 512; s > 0; s >>= 1) {
        if (threadIdx.x < s) red[threadIdx.x] += red[threadIdx.x + s];
        __syncthreads();
    }
    if (threadIdx.x == 0) out[0] = red[0] * (1.0f / (float)(BB*WW));
}

// ---------------- launch ----------------
extern "C" void kernel_launch(void* const* d_in, const int* in_sizes, int n_in,
                              void* d_out, int out_size)
{
    const float* pred   = (const float*)d_in[0];
    const float* labels = (const float*)d_in[1];
    if (n_in >= 2 && in_sizes[0] == BB*HW && in_sizes[1] == BB*CC*HW) {
        pred   = (const float*)d_in[1];
        labels = (const float*)d_in[0];
    }
    float* out = (float*)d_out;

    k_prepare<<<dim3(HW/4/256, BB), 256>>>(pred, labels);
    k_canny  <<<dim3(WW/32, HH/32, NPLANE), dim3(32, 32)>>>();
    k_merge  <<<(NPLANE*TPP + 255)/256, 256>>>();
    k_flag   <<<(NPLANE*HW/4)/256, 256>>>();
    k_edge   <<<(NPLANE*HW)/256, 256>>>();
    k_part   <<<dim3(NHC, BB), 512>>>();
    k_final  <<<1, 1024>>>(out);
}

// round 16
// speedup vs baseline: 1.1286x; 1.1286x over previous
#include <cuda_runtime.h>
#include <cuda_bf16.h>
#include <math.h>

// Problem constants
#define BB 8
#define CC 19
#define HH 512
#define WW 512
#define HW (HH*WW)          // 262144
#define NPLANE 16           // 8 pred-planes + 8 label-planes
#define NHC 64              // h-chunks in k_part (8 rows each)

// padded image: 2px clamp halo, pitch 528 (16B aligned), origin (2,4)
#define PPITCH 528
#define PROWS  516
#define PSIZE  (PROWS*PPITCH)

// ---------------- device scratch (static, no allocation) ----------------
__device__ unsigned char g_imgp[NPLANE*PSIZE];   // padded quantized images
__device__ unsigned char g_state[NPLANE*HW];     // 0/1/2 states, then edge bytes after k_edge
__device__ int           g_label[NPLANE*HW];     // union-find labels (valid where state>0)
__device__ unsigned char g_flag[NPLANE*HW];      // component-has-strong (by root)
__device__ int   g_pnp[NHC][BB*WW];
__device__ int   g_pnl[NHC][BB*WW];
__device__ int   g_pdt[NHC][BB*WW];
__device__ float g_colloss[BB*WW];

// write a quad + clamp-halo replicas into a padded plane
__device__ __forceinline__ void store_quad(unsigned char* plane, int y, int x, uchar4 q)
{
    int py = y + 2, px = x + 4;
    *reinterpret_cast<uchar4*>(plane + py*PPITCH + px) = q;
    bool top = (y == 0), bot = (y == HH-1);
    if (top) {
        *reinterpret_cast<uchar4*>(plane + 0*PPITCH + px) = q;
        *reinterpret_cast<uchar4*>(plane + 1*PPITCH + px) = q;
    }
    if (bot) {
        *reinterpret_cast<uchar4*>(plane + 514*PPITCH + px) = q;
        *reinterpret_cast<uchar4*>(plane + 515*PPITCH + px) = q;
    }
    if (x == 0) {
        uchar4 l = make_uchar4(q.x, q.x, q.x, q.x);
        *reinterpret_cast<uchar4*>(plane + py*PPITCH + 0) = l;
        if (top) { *reinterpret_cast<uchar4*>(plane + 0*PPITCH) = l;
                   *reinterpret_cast<uchar4*>(plane + 1*PPITCH) = l; }
        if (bot) { *reinterpret_cast<uchar4*>(plane + 514*PPITCH) = l;
                   *reinterpret_cast<uchar4*>(plane + 515*PPITCH) = l; }
    }
    if (x == WW-4) {
        uchar4 r = make_uchar4(q.w, q.w, q.w, q.w);
        *reinterpret_cast<uchar4*>(plane + py*PPITCH + 516) = r;
        if (top) { *reinterpret_cast<uchar4*>(plane + 0*PPITCH + 516) = r;
                   *reinterpret_cast<uchar4*>(plane + 1*PPITCH + 516) = r; }
        if (bot) { *reinterpret_cast<uchar4*>(plane + 514*PPITCH + 516) = r;
                   *reinterpret_cast<uchar4*>(plane + 515*PPITCH + 516) = r; }
    }
}

// ---------------- K1: argmax over C + quantize -> padded images (halo inline) ----------------
__global__ void k_prepare(const float* __restrict__ pred,
                          const float* __restrict__ labels)
{
    int b  = blockIdx.y;
    int i4 = blockIdx.x * blockDim.x + threadIdx.x;   // float4 index in HW/4
    if (i4 >= HW/4) return;

    const float4* base = reinterpret_cast<const float4*>(pred + (size_t)b*CC*HW) + i4;
    float4 best = base[0];
    int bx = 0, by = 0, bz = 0, bw = 0;
    #pragma unroll
    for (int c = 1; c < CC; c++) {
        float4 v = base[(size_t)c * (HW/4)];
        if (v.x > best.x) { best.x = v.x; bx = c; }
        if (v.y > best.y) { best.y = v.y; by = c; }
        if (v.z > best.z) { best.z = v.z; bz = c; }
        if (v.w > best.w) { best.w = v.w; bw = c; }
    }
    // (cls*255) % 256 == 0 if cls==0 else 256-cls  (cls in 0..18)
    uchar4 op;
    op.x = bx ? (unsigned char)(256 - bx) : 0;
    op.y = by ? (unsigned char)(256 - by) : 0;
    op.z = bz ? (unsigned char)(256 - bz) : 0;
    op.w = bw ? (unsigned char)(256 - bw) : 0;

    int pix = i4 * 4;
    int y = pix >> 9, x = pix & 511;
    store_quad(g_imgp + (size_t)b*PSIZE, y, x, op);

    float4 l = reinterpret_cast<const float4*>(labels + (size_t)b*HW)[i4];
    uchar4 ol;
    ol.x = (unsigned char)floorf(l.x * 255.0f);
    ol.y = (unsigned char)floorf(l.y * 255.0f);
    ol.z = (unsigned char)floorf(l.z * 255.0f);
    ol.w = (unsigned char)floorf(l.w * 255.0f);
    store_quad(g_imgp + (size_t)(8+b)*PSIZE, y, x, ol);
}

// ---------------- smem union-find (tile-local CCL) ----------------
__device__ __forceinline__ int findrootS(volatile int* L, int x)
{
    int p = L[x];
    while (p != x) { x = p; p = L[x]; }
    return p;
}

__device__ __forceinline__ void uniteS(volatile int* L, int a, int b)
{
    while (true) {
        a = findrootS(L, a);
        b = findrootS(L, b);
        if (a == b) return;
        if (a < b) { int t = a; a = b; b = t; }
        int old = atomicMin((int*)&L[a], b);
        if (old == a) return;
        a = old;
    }
}

// ---------------- K2: Sobel + NMS + tile-local union-find ----------------
// Sobel computed ONCE per pixel (mag stage also emits 2-bit direction code).
__global__ void k_canny()
{
    __shared__ unsigned int simg_u[36*10];   // 36 rows x 40 bytes
    __shared__ int          smag[34][36];
    __shared__ int          sdir[32][33];    // direction code 0..3, interior pixels
    __shared__ unsigned char sst[32][32];
    __shared__ int          sl[1024];
    unsigned char* simg = (unsigned char*)simg_u;

    const int plane = blockIdx.z;
    const int oy = blockIdx.y * 32;
    const int ox = blockIdx.x * 32;
    const int tx = threadIdx.x, ty = threadIdx.y;
    const int tid = ty * 32 + tx;
    const unsigned char* img = g_imgp + (size_t)plane * PSIZE;

    for (int i = tid; i < 360; i += 1024) {
        int sy = i / 10, j = i % 10;
        simg_u[sy*10 + j] =
            *reinterpret_cast<const unsigned int*>(img + (oy + sy)*PPITCH + ox + 4*j);
    }
    __syncthreads();

    // mag over 34x34 (zero outside image); also direction code for the 32x32 interior
    for (int i = tid; i < 34*34; i += 1024) {
        int sy = i / 34, sx = i % 34;
        int my = oy + sy - 1, mx = ox + sx - 1;
        int m = 0;
        int gxv = 0, gyv = 0;
        if (my >= 0 && my < HH && mx >= 0 && mx < WW) {
            const unsigned char* r0p = simg + sy*40 + sx + 2;
            const unsigned char* r1p = r0p + 40;
            const unsigned char* r2p = r1p + 40;
            int a00 = r0p[0], a01 = r0p[1], a02 = r0p[2];
            int a10 = r1p[0],               a12 = r1p[2];
            int a20 = r2p[0], a21 = r2p[1], a22 = r2p[2];
            gxv = (a02 + 2*a12 + a22) - (a00 + 2*a10 + a20);
            gyv = (a20 + 2*a21 + a22) - (a00 + 2*a01 + a02);
            m = abs(gxv) + abs(gyv);
        }
        smag[sy][sx] = m;
        if (sy >= 1 && sy <= 32 && sx >= 1 && sx <= 32) {
            // exact integer quantization of atan2 direction (mod 180)
            int a = abs(gxv);
            int gyn = gyv, sgx = gxv;
            if (gyn < 0) { gyn = -gyn; sgx = -sgx; }
            int u = gyn + a;
            bool d0  = (u*u < 2*a*a);                 // |tan| < tan22.5
            int v = gyn - a;
            bool lt2 = (v < 0) || (v*v < 2*a*a);      // |tan| < tan67.5
            int code;
            if (d0)                  code = 0;        // 0 deg
            else if (sgx > 0 && lt2) code = 1;        // 45
            else if (!lt2)           code = 2;        // 90
            else                     code = 3;        // 135
            sdir[sy-1][sx-1] = code;
        }
    }
    __syncthreads();

    // per-pixel NMS: read mag + dir, 2 neighbor compares
    {
        const int i1 = ty + 1, j1 = tx + 1;
        int m = smag[i1][j1];
        int code = sdir[ty][tx];
        bool keep;
        if (code == 0)      keep = (m >= smag[i1][j1+1])   && (m >= smag[i1][j1-1]);
        else if (code == 1) keep = (m >= smag[i1-1][j1+1]) && (m >= smag[i1+1][j1-1]);
        else if (code == 2) keep = (m >= smag[i1+1][j1])   && (m >= smag[i1-1][j1]);
        else                keep = (m >= smag[i1-1][j1-1]) && (m >= smag[i1+1][j1+1]);

        unsigned char st = 0;
        if (keep) { if (m > 200) st = 2; else if (m > 100) st = 1; }
        sst[ty][tx] = st;
    }
    sl[tid] = tid;
    __syncthreads();

    unsigned char st = sst[ty][tx];
    if (st) {
        if (tx > 0           && sst[ty][tx-1])   uniteS(sl, tid, tid-1);
        if (ty > 0) {
            if (tx > 0       && sst[ty-1][tx-1]) uniteS(sl, tid, tid-33);
            if (                sst[ty-1][tx])   uniteS(sl, tid, tid-32);
            if (tx < 31      && sst[ty-1][tx+1]) uniteS(sl, tid, tid-31);
        }
    }
    __syncthreads();

    int gidx = plane*HW + (oy+ty)*WW + (ox+tx);
    g_state[gidx] = st;
    if (st) {
        int root = findrootS(sl, tid);
        g_label[gidx] = plane*HW + (oy + (root >> 5))*WW + (ox + (root & 31));
        g_flag[gidx]  = 0;
    }
}

// ---------------- global union-find ----------------
__device__ __forceinline__ int findroot(int* L, int x)
{
    int p = __ldcg(&L[x]);
    while (p != x) { x = p; p = __ldcg(&L[x]); }
    return p;
}

__device__ __forceinline__ void unite(int* L, int a, int b)
{
    while (true) {
        a = findroot(L, a);
        b = findroot(L, b);
        if (a == b) return;
        if (a < b) { int t = a; a = b; b = t; }
        int old = atomicMin(&L[a], b);
        if (old == a) return;
        a = old;
    }
}

__device__ __forceinline__ int findhalve(int* L, int x)
{
    while (true) {
        int p = __ldcg(&L[x]);
        if (p == x) return x;
        int gp = __ldcg(&L[p]);
        if (gp == p) return p;
        L[x] = gp;
        x = gp;
    }
}

// ---------------- K3: cross-tile merges, compact boundary enumeration ----------------
#define TPP (8192 + 7680 + 7680)
__global__ void k_merge()
{
    int t = blockIdx.x * blockDim.x + threadIdx.x;
    if (t >= NPLANE*TPP) return;
    int plane = t / TPP;
    int i = t % TPP;

    int x, y;
    bool doW = false, doNW = false, doN = false, doNE = false;
    if (i < 8192) {
        y = (i >> 9) * 32; x = i & 511;
        doNW = doN = doNE = true; doW = ((x & 31) == 0);
    } else if (i < 8192 + 7680) {
        int j = i - 8192; y = j & 511; x = 32 * ((j >> 9) + 1);
        if ((y & 31) == 0) return;
        doW = doNW = true;
    } else {
        int j = i - 8192 - 7680; y = j & 511; x = 32 * (j >> 9) + 31;
        if ((y & 31) == 0) return;
        doNE = true;
    }

    int idx = plane*HW + y*WW + x;
    if (!g_state[idx]) return;
    if (doW && x > 0 && g_state[idx-1]) unite(g_label, idx, idx-1);
    if (y > 0) {
        if (doNW && x > 0    && g_state[idx-WW-1]) unite(g_label, idx, idx-WW-1);
        if (doN              && g_state[idx-WW])   unite(g_label, idx, idx-WW);
        if (doNE && x < WW-1 && g_state[idx-WW+1]) unite(g_label, idx, idx-WW+1);
    }
}

// ---------------- K4: mark strong components (4 px/thread — measured best) ----------------
__global__ void k_flag()
{
    int t = blockIdx.x * blockDim.x + threadIdx.x;
    if (t >= NPLANE*HW/4) return;
    unsigned int w = reinterpret_cast<const unsigned int*>(g_state)[t];
    if ((w & 0x02020202u) == 0) return;
    int base = t * 4;
    #pragma unroll
    for (int j = 0; j < 4; j++) {
        if ((w >> (8*j)) & 2u) {
            g_flag[findhalve(g_label, base + j)] = 1;
        }
    }
}

// ---------------- K4b: resolve pixels to edge bytes (1 px/thread) ----------------
__global__ void k_edge()
{
    int idx = blockIdx.x * blockDim.x + threadIdx.x;
    if (idx >= NPLANE*HW) return;
    unsigned char s = g_state[idx];
    unsigned char e = 0;
    if (s == 2) e = 1;
    else if (s == 1) e = g_flag[findhalve(g_label, idx)];
    g_state[idx] = e;      // in-place: g_state now holds edge map {0,1}
}

// ---------------- K5: per-column partial sums — pure streaming ----------------
__global__ void k_part()
{
    int b  = blockIdx.y;          // batch
    int hc = blockIdx.x;          // h-chunk of 8 rows
    int w  = threadIdx.x;         // 512 threads = one per column
    int np = 0, nl = 0, dt = 0;
    int base_p = b*HW       + hc*8*WW + w;
    int base_l = (8+b)*HW   + hc*8*WW + w;
    #pragma unroll
    for (int hh = 0; hh < 8; hh++) {
        int ep = g_state[base_p + hh*WW];
        int el = g_state[base_l + hh*WW];
        np += ep; nl += el; dt += (ep & el);
    }
    int col = b*WW + w;
    g_pnp[hc][col] = np;
    g_pnl[hc][col] = nl;
    g_pdt[hc][col] = dt;
}

// ---------------- K6a: per-column loss (parallel) ----------------
__global__ void k_colsum()
{
    int col = blockIdx.x * blockDim.x + threadIdx.x;   // 0..4095
    if (col >= BB*WW) return;
    int np = 0, nl = 0, dt = 0;
    #pragma unroll 8
    for (int hc = 0; hc < NHC; hc++) {
        np += g_pnp[hc][col];
        nl += g_pnl[hc][col];
        dt += g_pdt[hc][col];
    }
    float lse = logf(fmaf((float)np, 1.7182818284590452f, 512.0f));
    g_colloss[col] = (float)nl * lse - (float)dt;
}

// ---------------- K6b: final scalar (single block, deterministic) ----------------
__global__ void k_final(float* __restrict__ out)
{
    __shared__ float red[1024];
    float acc = 0.0f;
    #pragma unroll
    for (int k = 0; k < 4; k++)
        acc += g_colloss[threadIdx.x + k*1024];
    red[threadIdx.x] = acc;
    __syncthreads();
    for (int s = 512; s > 0; s >>= 1) {
        if (threadIdx.x < s) red[threadIdx.x] += red[threadIdx.x + s];
        __syncthreads();
    }
    if (threadIdx.x == 0) out[0] = red[0] * (1.0f / (float)(BB*WW));
}

// ---------------- launch ----------------
extern "C" void kernel_launch(void* const* d_in, const int* in_sizes, int n_in,
                              void* d_out, int out_size)
{
    const float* pred   = (const float*)d_in[0];
    const float* labels = (const float*)d_in[1];
    if (n_in >= 2 && in_sizes[0] == BB*HW && in_sizes[1] == BB*CC*HW) {
        pred   = (const float*)d_in[1];
        labels = (const float*)d_in[0];
    }
    float* out = (float*)d_out;

    k_prepare<<<dim3(HW/4/256, BB), 256>>>(pred, labels);
    k_canny  <<<dim3(WW/32, HH/32, NPLANE), dim3(32, 32)>>>();
    k_merge  <<<(NPLANE*TPP + 255)/256, 256>>>();
    k_flag   <<<(NPLANE*HW/4)/256, 256>>>();
    k_edge   <<<(NPLANE*HW)/256, 256>>>();
    k_part   <<<dim3(NHC, BB), 512>>>();
    k_colsum <<<BB*WW/512, 512>>>();
    k_final  <<<1, 1024>>>(out);
}

// round 17
// speedup vs baseline: 1.1682x; 1.0351x over previous
#include <cuda_runtime.h>
#include <cuda_bf16.h>
#include <math.h>

// Problem constants
#define BB 8
#define CC 19
#define HH 512
#define WW 512
#define HW (HH*WW)          // 262144
#define NPLANE 16           // 8 pred-planes + 8 label-planes
#define NHC 64              // h-chunks in k_part (8 rows each)

// padded image: 2px clamp halo, pitch 528 (16B aligned), origin (2,4)
#define PPITCH 528
#define PROWS  516
#define PSIZE  (PROWS*PPITCH)

// ---------------- device scratch (static, no allocation) ----------------
__device__ unsigned char g_imgp[NPLANE*PSIZE];   // padded quantized images
__device__ unsigned char g_state[NPLANE*HW];     // 0=none 1=weak 2=strong
__device__ int           g_label[NPLANE*HW];     // union-find labels (valid where state>0)
__device__ unsigned char g_flag[NPLANE*HW];      // component-has-strong (by root)
__device__ int   g_pnp[NHC][BB*WW];
__device__ int   g_pnl[NHC][BB*WW];
__device__ int   g_pdt[NHC][BB*WW];
__device__ float g_colloss[BB*WW];

// write a quad + clamp-halo replicas into a padded plane
__device__ __forceinline__ void store_quad(unsigned char* plane, int y, int x, uchar4 q)
{
    int py = y + 2, px = x + 4;
    *reinterpret_cast<uchar4*>(plane + py*PPITCH + px) = q;
    bool top = (y == 0), bot = (y == HH-1);
    if (top) {
        *reinterpret_cast<uchar4*>(plane + 0*PPITCH + px) = q;
        *reinterpret_cast<uchar4*>(plane + 1*PPITCH + px) = q;
    }
    if (bot) {
        *reinterpret_cast<uchar4*>(plane + 514*PPITCH + px) = q;
        *reinterpret_cast<uchar4*>(plane + 515*PPITCH + px) = q;
    }
    if (x == 0) {
        uchar4 l = make_uchar4(q.x, q.x, q.x, q.x);
        *reinterpret_cast<uchar4*>(plane + py*PPITCH + 0) = l;
        if (top) { *reinterpret_cast<uchar4*>(plane + 0*PPITCH) = l;
                   *reinterpret_cast<uchar4*>(plane + 1*PPITCH) = l; }
        if (bot) { *reinterpret_cast<uchar4*>(plane + 514*PPITCH) = l;
                   *reinterpret_cast<uchar4*>(plane + 515*PPITCH) = l; }
    }
    if (x == WW-4) {
        uchar4 r = make_uchar4(q.w, q.w, q.w, q.w);
        *reinterpret_cast<uchar4*>(plane + py*PPITCH + 516) = r;
        if (top) { *reinterpret_cast<uchar4*>(plane + 0*PPITCH + 516) = r;
                   *reinterpret_cast<uchar4*>(plane + 1*PPITCH + 516) = r; }
        if (bot) { *reinterpret_cast<uchar4*>(plane + 514*PPITCH + 516) = r;
                   *reinterpret_cast<uchar4*>(plane + 515*PPITCH + 516) = r; }
    }
}

// ---------------- K1: argmax over C + quantize -> padded images (halo inline) ----------------
__global__ void k_prepare(const float* __restrict__ pred,
                          const float* __restrict__ labels)
{
    int b  = blockIdx.y;
    int i4 = blockIdx.x * blockDim.x + threadIdx.x;   // float4 index in HW/4
    if (i4 >= HW/4) return;

    const float4* base = reinterpret_cast<const float4*>(pred + (size_t)b*CC*HW) + i4;
    float4 best = base[0];
    int bx = 0, by = 0, bz = 0, bw = 0;
    #pragma unroll
    for (int c = 1; c < CC; c++) {
        float4 v = base[(size_t)c * (HW/4)];
        if (v.x > best.x) { best.x = v.x; bx = c; }
        if (v.y > best.y) { best.y = v.y; by = c; }
        if (v.z > best.z) { best.z = v.z; bz = c; }
        if (v.w > best.w) { best.w = v.w; bw = c; }
    }
    // (cls*255) % 256 == 0 if cls==0 else 256-cls  (cls in 0..18)
    uchar4 op;
    op.x = bx ? (unsigned char)(256 - bx) : 0;
    op.y = by ? (unsigned char)(256 - by) : 0;
    op.z = bz ? (unsigned char)(256 - bz) : 0;
    op.w = bw ? (unsigned char)(256 - bw) : 0;

    int pix = i4 * 4;
    int y = pix >> 9, x = pix & 511;
    store_quad(g_imgp + (size_t)b*PSIZE, y, x, op);

    float4 l = reinterpret_cast<const float4*>(labels + (size_t)b*HW)[i4];
    uchar4 ol;
    ol.x = (unsigned char)floorf(l.x * 255.0f);
    ol.y = (unsigned char)floorf(l.y * 255.0f);
    ol.z = (unsigned char)floorf(l.z * 255.0f);
    ol.w = (unsigned char)floorf(l.w * 255.0f);
    store_quad(g_imgp + (size_t)(8+b)*PSIZE, y, x, ol);
}

// ---------------- smem union-find (tile-local CCL) ----------------
__device__ __forceinline__ int findrootS(volatile int* L, int x)
{
    int p = L[x];
    while (p != x) { x = p; p = L[x]; }
    return p;
}

__device__ __forceinline__ void uniteS(volatile int* L, int a, int b)
{
    while (true) {
        a = findrootS(L, a);
        b = findrootS(L, b);
        if (a == b) return;
        if (a < b) { int t = a; a = b; b = t; }
        int old = atomicMin((int*)&L[a], b);
        if (old == a) return;
        a = old;
    }
}

// ---------------- K2: Sobel + NMS + tile-local union-find ----------------
// Sobel computed ONCE per pixel (mag stage also emits 2-bit direction code).
__global__ void k_canny()
{
    __shared__ unsigned int simg_u[36*10];   // 36 rows x 40 bytes
    __shared__ int          smag[34][36];
    __shared__ int          sdir[32][33];    // direction code 0..3, interior pixels
    __shared__ unsigned char sst[32][32];
    __shared__ int          sl[1024];
    unsigned char* simg = (unsigned char*)simg_u;

    const int plane = blockIdx.z;
    const int oy = blockIdx.y * 32;
    const int ox = blockIdx.x * 32;
    const int tx = threadIdx.x, ty = threadIdx.y;
    const int tid = ty * 32 + tx;
    const unsigned char* img = g_imgp + (size_t)plane * PSIZE;

    for (int i = tid; i < 360; i += 1024) {
        int sy = i / 10, j = i % 10;
        simg_u[sy*10 + j] =
            *reinterpret_cast<const unsigned int*>(img + (oy + sy)*PPITCH + ox + 4*j);
    }
    __syncthreads();

    // mag over 34x34 (zero outside image); also direction code for the 32x32 interior
    for (int i = tid; i < 34*34; i += 1024) {
        int sy = i / 34, sx = i % 34;
        int my = oy + sy - 1, mx = ox + sx - 1;
        int m = 0;
        int gxv = 0, gyv = 0;
        if (my >= 0 && my < HH && mx >= 0 && mx < WW) {
            const unsigned char* r0p = simg + sy*40 + sx + 2;
            const unsigned char* r1p = r0p + 40;
            const unsigned char* r2p = r1p + 40;
            int a00 = r0p[0], a01 = r0p[1], a02 = r0p[2];
            int a10 = r1p[0],               a12 = r1p[2];
            int a20 = r2p[0], a21 = r2p[1], a22 = r2p[2];
            gxv = (a02 + 2*a12 + a22) - (a00 + 2*a10 + a20);
            gyv = (a20 + 2*a21 + a22) - (a00 + 2*a01 + a02);
            m = abs(gxv) + abs(gyv);
        }
        smag[sy][sx] = m;
        if (sy >= 1 && sy <= 32 && sx >= 1 && sx <= 32) {
            // exact integer quantization of atan2 direction (mod 180)
            int a = abs(gxv);
            int gyn = gyv, sgx = gxv;
            if (gyn < 0) { gyn = -gyn; sgx = -sgx; }
            int u = gyn + a;
            bool d0  = (u*u < 2*a*a);                 // |tan| < tan22.5
            int v = gyn - a;
            bool lt2 = (v < 0) || (v*v < 2*a*a);      // |tan| < tan67.5
            int code;
            if (d0)                  code = 0;        // 0 deg
            else if (sgx > 0 && lt2) code = 1;        // 45
            else if (!lt2)           code = 2;        // 90
            else                     code = 3;        // 135
            sdir[sy-1][sx-1] = code;
        }
    }
    __syncthreads();

    // per-pixel NMS: read mag + dir, 2 neighbor compares
    {
        const int i1 = ty + 1, j1 = tx + 1;
        int m = smag[i1][j1];
        int code = sdir[ty][tx];
        bool keep;
        if (code == 0)      keep = (m >= smag[i1][j1+1])   && (m >= smag[i1][j1-1]);
        else if (code == 1) keep = (m >= smag[i1-1][j1+1]) && (m >= smag[i1+1][j1-1]);
        else if (code == 2) keep = (m >= smag[i1+1][j1])   && (m >= smag[i1-1][j1]);
        else                keep = (m >= smag[i1-1][j1-1]) && (m >= smag[i1+1][j1+1]);

        unsigned char st = 0;
        if (keep) { if (m > 200) st = 2; else if (m > 100) st = 1; }
        sst[ty][tx] = st;
    }
    sl[tid] = tid;
    __syncthreads();

    unsigned char st = sst[ty][tx];
    if (st) {
        if (tx > 0           && sst[ty][tx-1])   uniteS(sl, tid, tid-1);
        if (ty > 0) {
            if (tx > 0       && sst[ty-1][tx-1]) uniteS(sl, tid, tid-33);
            if (                sst[ty-1][tx])   uniteS(sl, tid, tid-32);
            if (tx < 31      && sst[ty-1][tx+1]) uniteS(sl, tid, tid-31);
        }
    }
    __syncthreads();

    int gidx = plane*HW + (oy+ty)*WW + (ox+tx);
    g_state[gidx] = st;
    if (st) {
        int root = findrootS(sl, tid);
        g_label[gidx] = plane*HW + (oy + (root >> 5))*WW + (ox + (root & 31));
        g_flag[gidx]  = 0;
    }
}

// ---------------- global union-find ----------------
__device__ __forceinline__ int findroot(int* L, int x)
{
    int p = __ldcg(&L[x]);
    while (p != x) { x = p; p = __ldcg(&L[x]); }
    return p;
}

__device__ __forceinline__ void unite(int* L, int a, int b)
{
    while (true) {
        a = findroot(L, a);
        b = findroot(L, b);
        if (a == b) return;
        if (a < b) { int t = a; a = b; b = t; }
        int old = atomicMin(&L[a], b);
        if (old == a) return;
        a = old;
    }
}

__device__ __forceinline__ int findhalve(int* L, int x)
{
    while (true) {
        int p = __ldcg(&L[x]);
        if (p == x) return x;
        int gp = __ldcg(&L[p]);
        if (gp == p) return p;
        L[x] = gp;
        x = gp;
    }
}

// ---------------- K3: cross-tile merges, compact boundary enumeration ----------------
#define TPP (8192 + 7680 + 7680)
__global__ void k_merge()
{
    int t = blockIdx.x * blockDim.x + threadIdx.x;
    if (t >= NPLANE*TPP) return;
    int plane = t / TPP;
    int i = t % TPP;

    int x, y;
    bool doW = false, doNW = false, doN = false, doNE = false;
    if (i < 8192) {
        y = (i >> 9) * 32; x = i & 511;
        doNW = doN = doNE = true; doW = ((x & 31) == 0);
    } else if (i < 8192 + 7680) {
        int j = i - 8192; y = j & 511; x = 32 * ((j >> 9) + 1);
        if ((y & 31) == 0) return;
        doW = doNW = true;
    } else {
        int j = i - 8192 - 7680; y = j & 511; x = 32 * (j >> 9) + 31;
        if ((y & 31) == 0) return;
        doNE = true;
    }

    int idx = plane*HW + y*WW + x;
    if (!g_state[idx]) return;
    if (doW && x > 0 && g_state[idx-1]) unite(g_label, idx, idx-1);
    if (y > 0) {
        if (doNW && x > 0    && g_state[idx-WW-1]) unite(g_label, idx, idx-WW-1);
        if (doN              && g_state[idx-WW])   unite(g_label, idx, idx-WW);
        if (doNE && x < WW-1 && g_state[idx-WW+1]) unite(g_label, idx, idx-WW+1);
    }
}

// ---------------- K4: mark strong components (4 px/thread — measured best) ----------------
__global__ void k_flag()
{
    int t = blockIdx.x * blockDim.x + threadIdx.x;
    if (t >= NPLANE*HW/4) return;
    unsigned int w = reinterpret_cast<const unsigned int*>(g_state)[t];
    if ((w & 0x02020202u) == 0) return;
    int base = t * 4;
    #pragma unroll
    for (int j = 0; j < 4; j++) {
        if ((w >> (8*j)) & 2u) {
            g_flag[findhalve(g_label, base + j)] = 1;
        }
    }
}

// ---------------- K5: fused edge-resolve + per-column partial sums ----------------
// One wave: 512 blocks x 512 threads = 262K threads, all resident at once.
__global__ void k_part()
{
    int b  = blockIdx.y;          // batch
    int hc = blockIdx.x;          // h-chunk of 8 rows
    int w  = threadIdx.x;         // 512 threads = one per column
    int np = 0, nl = 0, dt = 0;
    int base_p = b*HW       + hc*8*WW + w;
    int base_l = (8+b)*HW   + hc*8*WW + w;
    #pragma unroll
    for (int hh = 0; hh < 8; hh++) {
        int ip = base_p + hh*WW;
        int il = base_l + hh*WW;
        int sp = g_state[ip];
        int sl = g_state[il];
        int e1 = (sp & 2) ? 1 : (sp ? (int)g_flag[findhalve(g_label, ip)] : 0);
        int e2 = (sl & 2) ? 1 : (sl ? (int)g_flag[findhalve(g_label, il)] : 0);
        np += e1; nl += e2; dt += (e1 & e2);
    }
    int col = b*WW + w;
    g_pnp[hc][col] = np;
    g_pnl[hc][col] = nl;
    g_pdt[hc][col] = dt;
}

// ---------------- K6a: per-column loss (parallel) ----------------
__global__ void k_colsum()
{
    int col = blockIdx.x * blockDim.x + threadIdx.x;   // 0..4095
    if (col >= BB*WW) return;
    int np = 0, nl = 0, dt = 0;
    #pragma unroll 8
    for (int hc = 0; hc < NHC; hc++) {
        np += g_pnp[hc][col];
        nl += g_pnl[hc][col];
        dt += g_pdt[hc][col];
    }
    float lse = logf(fmaf((float)np, 1.7182818284590452f, 512.0f));
    g_colloss[col] = (float)nl * lse - (float)dt;
}

// ---------------- K6b: final scalar (single block, deterministic) ----------------
__global__ void k_final(float* __restrict__ out)
{
    __shared__ float red[1024];
    float acc = 0.0f;
    #pragma unroll
    for (int k = 0; k < 4; k++)
        acc += g_colloss[threadIdx.x + k*1024];
    red[threadIdx.x] = acc;
    __syncthreads();
    for (int s = 512; s > 0; s >>= 1) {
        if (threadIdx.x < s) red[threadIdx.x] += red[threadIdx.x + s];
        __syncthreads();
    }
    if (threadIdx.x == 0) out[0] = red[0] * (1.0f / (float)(BB*WW));
}

// ---------------- launch ----------------
extern "C" void kernel_launch(void* const* d_in, const int* in_sizes, int n_in,
                              void* d_out, int out_size)
{
    const float* pred   = (const float*)d_in[0];
    const float* labels = (const float*)d_in[1];
    if (n_in >= 2 && in_sizes[0] == BB*HW && in_sizes[1] == BB*CC*HW) {
        pred   = (const float*)d_in[1];
        labels = (const float*)d_in[0];
    }
    float* out = (float*)d_out;

    k_prepare<<<dim3(HW/4/256, BB), 256>>>(pred, labels);
    k_canny  <<<dim3(WW/32, HH/32, NPLANE), dim3(32, 32)>>>();
    k_merge  <<<(NPLANE*TPP + 255)/256, 256>>>();
    k_flag   <<<(NPLANE*HW/4)/256, 256>>>();
    k_part   <<<dim3(NHC, BB), 512>>>();
    k_colsum <<<BB*WW/512, 512>>>();
    k_final  <<<1, 1024>>>(out);
}